// round 1
// baseline (speedup 1.0000x reference)
#include <cuda_runtime.h>
#include <math.h>
#include <stddef.h>

// Problem dims (fixed by the reference)
#define BB   8
#define SS   1024
#define DD   1024
#define HH   16
#define DHH  64
#define FF   4096
#define MR   (BB*SS)   // 8192 rows

// ---------------- scratch (device globals; no allocation allowed) ----------
__device__ float g_q  [MR*DD];
__device__ float g_k  [MR*DD];
__device__ float g_v  [MR*DD];
__device__ float g_ctx[MR*DD];
__device__ float g_t1 [MR*DD];
__device__ float g_x1 [MR*DD];
__device__ float g_h  [MR*FF];

// ---------------- GEMM: C[M,N] = A[M,K] @ B[K,N] + bias, optional ReLU -----
// Classic 128x128x8 tile, 256 threads, 8x8 microtile per thread.
// All dims are exact multiples of the tiles (M=8192, N/K in {1024,4096}).
template<int ACT>
__global__ __launch_bounds__(256) void sgemm_bias(
    const float* __restrict__ A, const float* __restrict__ B,
    const float* __restrict__ bias, float* __restrict__ C,
    int M, int N, int K)
{
    const int BM = 128, BN = 128, BK = 8, TM = 8, TN = 8;
    __shared__ float As[BK][BM];
    __shared__ float Bs[BK][BN];

    const int tid = threadIdx.x;
    const int tx  = tid & 15;        // 0..15
    const int ty  = tid >> 4;        // 0..15
    const int bc  = blockIdx.x;      // col tile
    const int br  = blockIdx.y;      // row tile

    A += (size_t)br * BM * K;
    B += (size_t)bc * BN;
    C += (size_t)br * BM * N + (size_t)bc * BN;

    const int aRow = tid >> 1;            // 0..127
    const int aCol = (tid & 1) * 4;       // 0 or 4
    const int bRow = tid >> 5;            // 0..7
    const int bCol = (tid & 31) * 4;      // 0..124

    float acc[TM][TN];
    #pragma unroll
    for (int i = 0; i < TM; i++)
        #pragma unroll
        for (int j = 0; j < TN; j++) acc[i][j] = 0.f;

    for (int k0 = 0; k0 < K; k0 += BK) {
        float4 av = *(const float4*)(A + (size_t)aRow * K + aCol);
        As[aCol + 0][aRow] = av.x;
        As[aCol + 1][aRow] = av.y;
        As[aCol + 2][aRow] = av.z;
        As[aCol + 3][aRow] = av.w;
        float4 bv = *(const float4*)(B + (size_t)bRow * N + bCol);
        *(float4*)(&Bs[bRow][bCol]) = bv;
        __syncthreads();

        #pragma unroll
        for (int kk = 0; kk < BK; kk++) {
            float ra[TM], rb[TN];
            *(float4*)(&ra[0]) = *(const float4*)(&As[kk][ty * TM + 0]);
            *(float4*)(&ra[4]) = *(const float4*)(&As[kk][ty * TM + 4]);
            *(float4*)(&rb[0]) = *(const float4*)(&Bs[kk][tx * TN + 0]);
            *(float4*)(&rb[4]) = *(const float4*)(&Bs[kk][tx * TN + 4]);
            #pragma unroll
            for (int i = 0; i < TM; i++)
                #pragma unroll
                for (int j = 0; j < TN; j++)
                    acc[i][j] += ra[i] * rb[j];
        }
        __syncthreads();
        A += BK;
        B += (size_t)BK * N;
    }

    // epilogue: bias (+ReLU), vectorized stores
    #pragma unroll
    for (int i = 0; i < TM; i++) {
        const int row = ty * TM + i;
        #pragma unroll
        for (int j = 0; j < TN; j += 4) {
            const int col = tx * TN + j;
            float4 bv = *(const float4*)(bias + (size_t)bc * BN + col);
            float4 o;
            o.x = acc[i][j + 0] + bv.x;
            o.y = acc[i][j + 1] + bv.y;
            o.z = acc[i][j + 2] + bv.z;
            o.w = acc[i][j + 3] + bv.w;
            if (ACT) {
                o.x = fmaxf(o.x, 0.f); o.y = fmaxf(o.y, 0.f);
                o.z = fmaxf(o.z, 0.f); o.w = fmaxf(o.w, 0.f);
            }
            *(float4*)(C + (size_t)row * N + col) = o;
        }
    }
}

// ---------------- Flash attention (fp32, online softmax) -------------------
// Block = one (b,h) and a 64-query tile. 256 threads = 8 warps.
// Thread (ty,tx) = (tid>>4, tid&15) owns a 4x4 microtile.
// Warp w owns query rows [8w, 8w+8): its threads have ty in {2w,2w+1},
// so S-tile writes, softmax and O-rescale for those rows are warp-local.
__global__ __launch_bounds__(256) void attn_kernel(
    const float* __restrict__ Q, const float* __restrict__ K,
    const float* __restrict__ V, const float* __restrict__ mask,
    float* __restrict__ O)
{
    extern __shared__ float sm[];
    float* Qs   = sm;                 // [64][64]
    float* Ks   = Qs + 64 * 64;      // [64][65] (pad: conflict-free col reads)
    float* Vs   = Ks + 64 * 65;      // [64][65]
    float* Sx   = Vs + 64 * 65;      // [64][64]
    float* mrow = Sx + 64 * 64;      // [64]
    float* lrow = mrow + 64;         // [64]
    float* frow = lrow + 64;         // [64]

    const int tid  = threadIdx.x;
    const int tx   = tid & 15;
    const int ty   = tid >> 4;
    const int lane = tid & 31;
    const int warp = tid >> 5;

    const int qt = blockIdx.x;            // 0..15 query tile
    const int bh = blockIdx.y;            // 0..127
    const int b  = bh / HH;
    const int h  = bh % HH;

    const float* qbase = Q + ((size_t)b * SS + (size_t)qt * 64) * DD + h * DHH;
    const float* kbase = K + (size_t)b * SS * DD + h * DHH;
    const float* vbase = V + (size_t)b * SS * DD + h * DHH;
    const float* mbase = mask + (size_t)b * SS;

    // Load Q tile [64 x 64]
    for (int i = tid; i < 64 * 16; i += 256) {
        int r = i >> 4, c4 = (i & 15) * 4;
        *(float4*)(Qs + r * 64 + c4) =
            *(const float4*)(qbase + (size_t)r * DD + c4);
    }
    if (tid < 64) { mrow[tid] = -INFINITY; lrow[tid] = 0.f; }

    float o[4][4];
    #pragma unroll
    for (int i = 0; i < 4; i++)
        #pragma unroll
        for (int j = 0; j < 4; j++) o[i][j] = 0.f;

    for (int t = 0; t < 16; t++) {
        __syncthreads();   // previous iter done reading Ks/Vs (and Qs loaded)
        // Load K and V tiles [64 keys x 64 dh]
        const float* kp = kbase + (size_t)(t * 64) * DD;
        const float* vp = vbase + (size_t)(t * 64) * DD;
        for (int i = tid; i < 64 * 16; i += 256) {
            int r = i >> 4, c4 = (i & 15) * 4;
            float4 kv = *(const float4*)(kp + (size_t)r * DD + c4);
            float* kd = Ks + r * 65 + c4;
            kd[0] = kv.x; kd[1] = kv.y; kd[2] = kv.z; kd[3] = kv.w;
            float4 vv = *(const float4*)(vp + (size_t)r * DD + c4);
            float* vd = Vs + r * 65 + c4;
            vd[0] = vv.x; vd[1] = vv.y; vd[2] = vv.z; vd[3] = vv.w;
        }
        __syncthreads();

        // S = Q @ K^T  (4x4 microtile over dh=64)
        float s[4][4];
        #pragma unroll
        for (int i = 0; i < 4; i++)
            #pragma unroll
            for (int j = 0; j < 4; j++) s[i][j] = 0.f;
        #pragma unroll 8
        for (int kk = 0; kk < 64; kk++) {
            float ra[4], rb[4];
            #pragma unroll
            for (int i = 0; i < 4; i++) ra[i] = Qs[(ty * 4 + i) * 64 + kk];
            #pragma unroll
            for (int j = 0; j < 4; j++) rb[j] = Ks[(tx * 4 + j) * 65 + kk];
            #pragma unroll
            for (int i = 0; i < 4; i++)
                #pragma unroll
                for (int j = 0; j < 4; j++)
                    s[i][j] += ra[i] * rb[j];
        }

        // scale + mask, write to smem S tile (warp-local rows)
        #pragma unroll
        for (int i = 0; i < 4; i++)
            #pragma unroll
            for (int j = 0; j < 4; j++) {
                int kcol = t * 64 + tx * 4 + j;
                Sx[(ty * 4 + i) * 64 + tx * 4 + j] =
                    s[i][j] * 0.125f + mbase[kcol] * (-1e9f);
            }
        __syncwarp();

        // online softmax: warp handles its 8 rows (2 cols per lane)
        #pragma unroll
        for (int rr = 0; rr < 8; rr++) {
            int r = warp * 8 + rr;
            float v0 = Sx[r * 64 + lane];
            float v1 = Sx[r * 64 + 32 + lane];
            float tm = fmaxf(v0, v1);
            #pragma unroll
            for (int off = 16; off; off >>= 1)
                tm = fmaxf(tm, __shfl_xor_sync(0xffffffffu, tm, off));
            float mprev = mrow[r];
            float nm = fmaxf(mprev, tm);
            float e0 = __expf(v0 - nm);
            float e1 = __expf(v1 - nm);
            Sx[r * 64 + lane]      = e0;
            Sx[r * 64 + 32 + lane] = e1;
            float sum = e0 + e1;
            #pragma unroll
            for (int off = 16; off; off >>= 1)
                sum += __shfl_xor_sync(0xffffffffu, sum, off);
            if (lane == 0) {
                float f = __expf(mprev - nm);
                frow[r] = f;
                lrow[r] = lrow[r] * f + sum;
                mrow[r] = nm;
            }
        }
        __syncwarp();

        // rescale O accumulators (own rows)
        float f[4];
        #pragma unroll
        for (int i = 0; i < 4; i++) f[i] = frow[ty * 4 + i];
        #pragma unroll
        for (int i = 0; i < 4; i++)
            #pragma unroll
            for (int j = 0; j < 4; j++) o[i][j] *= f[i];

        // O += P @ V
        #pragma unroll 8
        for (int kk = 0; kk < 64; kk++) {
            float ra[4], rb[4];
            #pragma unroll
            for (int i = 0; i < 4; i++) ra[i] = Sx[(ty * 4 + i) * 64 + kk];
            #pragma unroll
            for (int j = 0; j < 4; j++) rb[j] = Vs[kk * 65 + tx * 4 + j];
            #pragma unroll
            for (int i = 0; i < 4; i++)
                #pragma unroll
                for (int j = 0; j < 4; j++)
                    o[i][j] += ra[i] * rb[j];
        }
    }

    // normalize and write ctx in [B,S,D] layout
    #pragma unroll
    for (int i = 0; i < 4; i++) {
        int row = ty * 4 + i;
        float linv = 1.f / lrow[row];
        float4 ov;
        ov.x = o[i][0] * linv;
        ov.y = o[i][1] * linv;
        ov.z = o[i][2] * linv;
        ov.w = o[i][3] * linv;
        size_t idx = ((size_t)b * SS + (size_t)qt * 64 + row) * DD
                   + h * DHH + tx * 4;
        *(float4*)(O + idx) = ov;
    }
}

// ---------------- residual + LayerNorm -------------------------------------
__global__ __launch_bounds__(256) void residual_ln_kernel(
    const float* __restrict__ X, const float* __restrict__ Y,
    const float* __restrict__ g, const float* __restrict__ beta,
    float* __restrict__ out)
{
    __shared__ float ws[8], ws2[8];
    const int row = blockIdx.x;
    const int tid = threadIdx.x;
    const int lane = tid & 31, warp = tid >> 5;
    const float* px = X + (size_t)row * DD;
    const float* py = Y + (size_t)row * DD;

    float v[4];
    float s = 0.f, s2 = 0.f;
    #pragma unroll
    for (int l = 0; l < 4; l++) {
        int c = tid + l * 256;
        float t = px[c] + py[c];
        v[l] = t; s += t; s2 += t * t;
    }
    #pragma unroll
    for (int off = 16; off; off >>= 1) {
        s  += __shfl_xor_sync(0xffffffffu, s,  off);
        s2 += __shfl_xor_sync(0xffffffffu, s2, off);
    }
    if (lane == 0) { ws[warp] = s; ws2[warp] = s2; }
    __syncthreads();
    if (warp == 0) {
        s  = (lane < 8) ? ws[lane]  : 0.f;
        s2 = (lane < 8) ? ws2[lane] : 0.f;
        #pragma unroll
        for (int off = 4; off; off >>= 1) {
            s  += __shfl_xor_sync(0xffffffffu, s,  off);
            s2 += __shfl_xor_sync(0xffffffffu, s2, off);
        }
        if (lane == 0) { ws[0] = s; ws2[0] = s2; }
    }
    __syncthreads();
    float mu  = ws[0] * (1.f / 1024.f);
    float var = fmaxf(ws2[0] * (1.f / 1024.f) - mu * mu, 0.f);
    float rstd = rsqrtf(var + 1e-6f);
    #pragma unroll
    for (int l = 0; l < 4; l++) {
        int c = tid + l * 256;
        out[(size_t)row * DD + c] = g[c] * (v[l] - mu) * rstd + beta[c];
    }
}

// ---------------- launch ----------------------------------------------------
extern "C" void kernel_launch(void* const* d_in, const int* in_sizes, int n_in,
                              void* d_out, int out_size)
{
    const float* x    = (const float*)d_in[0];
    const float* mask = (const float*)d_in[1];
    const float* Wq   = (const float*)d_in[2];
    const float* bq   = (const float*)d_in[3];
    const float* Wk   = (const float*)d_in[4];
    const float* bk   = (const float*)d_in[5];
    const float* Wv   = (const float*)d_in[6];
    const float* bv   = (const float*)d_in[7];
    const float* Wo   = (const float*)d_in[8];
    const float* bo   = (const float*)d_in[9];
    const float* g1   = (const float*)d_in[10];
    const float* be1  = (const float*)d_in[11];
    const float* W1   = (const float*)d_in[12];
    const float* bf1  = (const float*)d_in[13];
    const float* W2   = (const float*)d_in[14];
    const float* bf2  = (const float*)d_in[15];
    const float* g2   = (const float*)d_in[16];
    const float* be2  = (const float*)d_in[17];
    float* out = (float*)d_out;

    float *q, *k, *v, *ctx, *t1, *x1, *hbuf;
    cudaGetSymbolAddress((void**)&q,    g_q);
    cudaGetSymbolAddress((void**)&k,    g_k);
    cudaGetSymbolAddress((void**)&v,    g_v);
    cudaGetSymbolAddress((void**)&ctx,  g_ctx);
    cudaGetSymbolAddress((void**)&t1,   g_t1);
    cudaGetSymbolAddress((void**)&x1,   g_x1);
    cudaGetSymbolAddress((void**)&hbuf, g_h);

    const int attn_smem = (64 * 64 + 64 * 65 + 64 * 65 + 64 * 64 + 192) * 4;
    cudaFuncSetAttribute(attn_kernel,
                         cudaFuncAttributeMaxDynamicSharedMemorySize,
                         attn_smem);

    dim3 gD(DD / 128, MR / 128);   // (8, 64)
    dim3 gF(FF / 128, MR / 128);   // (32, 64)

    // QKV projections
    sgemm_bias<0><<<gD, 256>>>(x, Wq, bq, q, MR, DD, DD);
    sgemm_bias<0><<<gD, 256>>>(x, Wk, bk, k, MR, DD, DD);
    sgemm_bias<0><<<gD, 256>>>(x, Wv, bv, v, MR, DD, DD);

    // fused attention -> ctx [B,S,D]
    attn_kernel<<<dim3(16, 128), 256, attn_smem>>>(q, k, v, mask, ctx);

    // output projection + residual LN
    sgemm_bias<0><<<gD, 256>>>(ctx, Wo, bo, t1, MR, DD, DD);
    residual_ln_kernel<<<MR, 256>>>(x, t1, g1, be1, x1);

    // FFN
    sgemm_bias<1><<<gF, 256>>>(x1, W1, bf1, hbuf, MR, FF, DD);
    sgemm_bias<0><<<gD, 256>>>(hbuf, W2, bf2, t1, MR, DD, FF);
    residual_ln_kernel<<<MR, 256>>>(x1, t1, g2, be2, out);
}

// round 3
// speedup vs baseline: 2.2097x; 2.2097x over previous
#include <cuda_runtime.h>
#include <cuda_bf16.h>
#include <math.h>
#include <stddef.h>
#include <stdint.h>

// Problem dims (fixed by the reference)
#define BB   8
#define SS   1024
#define DD   1024
#define HH   16
#define DHH  64
#define FF   4096
#define MR   (BB*SS)   // 8192 rows

// ---------------- scratch (device globals; no allocation allowed) ----------
__device__ float g_q  [MR*DD];
__device__ float g_k  [MR*DD];
__device__ float g_v  [MR*DD];
__device__ float g_ctx[MR*DD];
__device__ float g_t1 [MR*DD];
__device__ float g_x1 [MR*DD];

// bf16 split buffers
__device__ __nv_bfloat16 g_ah[MR*DD];            // activation hi
__device__ __nv_bfloat16 g_al[MR*DD];            // activation lo
__device__ __nv_bfloat16 g_hh[(size_t)MR*FF];    // FFN hidden hi
__device__ __nv_bfloat16 g_hl[(size_t)MR*FF];    // FFN hidden lo
__device__ __nv_bfloat16 g_wh[(size_t)DD*FF];    // weight hi, [N,K]
__device__ __nv_bfloat16 g_wl[(size_t)DD*FF];    // weight lo, [N,K]

// ================= PTX helpers (compute_103-safe: sm_80 features only) =====
__device__ __forceinline__ uint32_t smem_u32(const void* p) {
    uint32_t a;
    asm("{ .reg .u64 t; cvta.to.shared.u64 t, %1; cvt.u32.u64 %0, t; }"
        : "=r"(a) : "l"(p));
    return a;
}
__device__ __forceinline__ uint32_t sw128(uint32_t o) {
    return o ^ ((o >> 3) & 0x70);
}
__device__ __forceinline__ void cp16(uint32_t s, const void* g) {
    asm volatile("cp.async.cg.shared.global [%0], [%1], 16;" :: "r"(s), "l"(g));
}
#define CP_COMMIT()  asm volatile("cp.async.commit_group;" ::: "memory")
#define CP_WAIT0()   asm volatile("cp.async.wait_group 0;" ::: "memory")
#define CP_WAIT1()   asm volatile("cp.async.wait_group 1;" ::: "memory")

__device__ __forceinline__ void ldsm4(uint32_t* r, uint32_t addr) {
    asm volatile("ldmatrix.sync.aligned.m8n8.x4.shared.b16 {%0,%1,%2,%3}, [%4];"
                 : "=r"(r[0]), "=r"(r[1]), "=r"(r[2]), "=r"(r[3]) : "r"(addr));
}
__device__ __forceinline__ void mma16816(float* d, const uint32_t* a,
                                         const uint32_t* b) {
    asm volatile(
        "mma.sync.aligned.m16n8k16.row.col.f32.bf16.bf16.f32 "
        "{%0,%1,%2,%3}, {%4,%5,%6,%7}, {%8,%9}, {%0,%1,%2,%3};"
        : "+f"(d[0]), "+f"(d[1]), "+f"(d[2]), "+f"(d[3])
        : "r"(a[0]), "r"(a[1]), "r"(a[2]), "r"(a[3]),
          "r"(b[0]), "r"(b[1]));
}

// ================= mma.sync GEMM ============================================
// C[M,N] = (Ah+Al)[M,K] @ (Bh+Bl)^T   (B stored [N,K] K-major) + bias
// 3-term bf16 emulation of fp32: hi*hi + lo*hi + hi*lo.
// CTA 128x128, BK=64, 8 warps (4x2), warp tile 32x64, double-buffered cp.async.
#define G_STAGE  65536            // Ah 16K | Al 16K | Bh 16K | Bl 16K
#define G_SMEM   (2*G_STAGE)

template<int ACT, int SPLITOUT>
__global__ __launch_bounds__(256)
void gemm_mma(const __nv_bfloat16* __restrict__ Ah,
              const __nv_bfloat16* __restrict__ Al,
              const __nv_bfloat16* __restrict__ Bh,
              const __nv_bfloat16* __restrict__ Bl,
              const float* __restrict__ bias,
              float* __restrict__ C,
              __nv_bfloat16* __restrict__ Ch,
              __nv_bfloat16* __restrict__ Cl,
              int N, int K)
{
    extern __shared__ __align__(128) char smem[];
    const uint32_t sb = smem_u32(smem);
    const int tid  = threadIdx.x;
    const int wid  = tid >> 5;
    const int lane = tid & 31;
    const int wm   = wid & 3;        // 0..3 over M
    const int wn   = wid >> 2;       // 0..1 over N
    const int bc = blockIdx.x, br = blockIdx.y;

    const __nv_bfloat16* Ah_t = Ah + (size_t)br * 128 * K;
    const __nv_bfloat16* Al_t = Al + (size_t)br * 128 * K;
    const __nv_bfloat16* Bh_t = Bh + (size_t)bc * 128 * K;
    const __nv_bfloat16* Bl_t = Bl + (size_t)bc * 128 * K;
    const int NT = K >> 6;

    // per-thread cp.async coords: 2 rows-chunks per matrix per iter
    auto load_stage = [&](int kt, int s) {
        const uint32_t base = sb + s * G_STAGE;
        const int koff = kt * 64;
        #pragma unroll
        for (int t = 0; t < 4; t++) {
            int idx = t * 256 + tid;           // 0..1023
            int row = idx >> 3, ch = idx & 7;
            uint32_t so = sw128((uint32_t)(row * 128 + ch * 16));
            size_t go = (size_t)row * K + koff + ch * 8;
            cp16(base +         so, Ah_t + go);
            cp16(base + 16384 + so, Al_t + go);
            cp16(base + 32768 + so, Bh_t + go);
            cp16(base + 49152 + so, Bl_t + go);
        }
        CP_COMMIT();
    };

    float acc[2][8][4];
    #pragma unroll
    for (int mi = 0; mi < 2; mi++)
        #pragma unroll
        for (int nj = 0; nj < 8; nj++)
            #pragma unroll
            for (int e = 0; e < 4; e++) acc[mi][nj][e] = 0.f;

    const int g = lane >> 3, r = lane & 7;

    load_stage(0, 0);

    for (int kt = 0; kt < NT; kt++) {
        const int buf = kt & 1;
        if (kt + 1 < NT) { load_stage(kt + 1, buf ^ 1); CP_WAIT1(); }
        else             { CP_WAIT0(); }
        __syncthreads();

        const uint32_t sA = sb + buf * G_STAGE;
        const uint32_t sAl = sA + 16384;
        const uint32_t sBh = sA + 32768;
        const uint32_t sBl = sA + 49152;

        #pragma unroll
        for (int kc = 0; kc < 4; kc++) {
            // A fragments (hi, lo): 2 m16 tiles
            uint32_t a_h[2][4], a_l[2][4];
            #pragma unroll
            for (int mi = 0; mi < 2; mi++) {
                int arow = wm * 32 + mi * 16 + r + ((g & 1) << 3);
                uint32_t off = sw128((uint32_t)(arow * 128 + kc * 32 +
                                                ((g >> 1) << 4)));
                ldsm4(a_h[mi], sA  + off);
                ldsm4(a_l[mi], sAl + off);
            }
            // B fragments in pairs of n8 tiles
            #pragma unroll
            for (int np = 0; np < 4; np++) {
                int brow = wn * 64 + np * 16 + r + ((g >> 1) << 3);
                uint32_t off = sw128((uint32_t)(brow * 128 + kc * 32 +
                                                ((g & 1) << 4)));
                uint32_t b_h[4], b_l[4];
                ldsm4(b_h, sBh + off);
                ldsm4(b_l, sBl + off);
                #pragma unroll
                for (int t = 0; t < 2; t++) {
                    int nj = np * 2 + t;
                    #pragma unroll
                    for (int mi = 0; mi < 2; mi++) {
                        mma16816(acc[mi][nj], a_h[mi], &b_h[2 * t]);
                        mma16816(acc[mi][nj], a_l[mi], &b_h[2 * t]);
                        mma16816(acc[mi][nj], a_h[mi], &b_l[2 * t]);
                    }
                }
            }
        }
        __syncthreads();
    }

    // epilogue: bias (+ReLU) (+bf16 hi/lo split)
    const int cbase = bc * 128 + wn * 64 + (lane & 3) * 2;
    const int rbase = br * 128 + wm * 32 + (lane >> 2);
    #pragma unroll
    for (int mi = 0; mi < 2; mi++) {
        #pragma unroll
        for (int nj = 0; nj < 8; nj++) {
            int c = cbase + nj * 8;
            float2 bv = *(const float2*)(bias + c);
            float v0 = acc[mi][nj][0] + bv.x;
            float v1 = acc[mi][nj][1] + bv.y;
            float v2 = acc[mi][nj][2] + bv.x;
            float v3 = acc[mi][nj][3] + bv.y;
            if (ACT) {
                v0 = fmaxf(v0, 0.f); v1 = fmaxf(v1, 0.f);
                v2 = fmaxf(v2, 0.f); v3 = fmaxf(v3, 0.f);
            }
            size_t i0 = (size_t)(rbase + mi * 16)     * N + c;
            size_t i1 = (size_t)(rbase + mi * 16 + 8) * N + c;
            if (SPLITOUT) {
                __nv_bfloat16 h0 = __float2bfloat16(v0);
                __nv_bfloat16 h1 = __float2bfloat16(v1);
                __nv_bfloat16 h2 = __float2bfloat16(v2);
                __nv_bfloat16 h3 = __float2bfloat16(v3);
                __nv_bfloat162 hp0; hp0.x = h0; hp0.y = h1;
                __nv_bfloat162 hp1; hp1.x = h2; hp1.y = h3;
                __nv_bfloat162 lp0;
                lp0.x = __float2bfloat16(v0 - __bfloat162float(h0));
                lp0.y = __float2bfloat16(v1 - __bfloat162float(h1));
                __nv_bfloat162 lp1;
                lp1.x = __float2bfloat16(v2 - __bfloat162float(h2));
                lp1.y = __float2bfloat16(v3 - __bfloat162float(h3));
                *(__nv_bfloat162*)(Ch + i0) = hp0;
                *(__nv_bfloat162*)(Ch + i1) = hp1;
                *(__nv_bfloat162*)(Cl + i0) = lp0;
                *(__nv_bfloat162*)(Cl + i1) = lp1;
            } else {
                float2 o0; o0.x = v0; o0.y = v1;
                float2 o1; o1.x = v2; o1.y = v3;
                *(float2*)(C + i0) = o0;
                *(float2*)(C + i1) = o1;
            }
        }
    }
}

// ================= fp32 -> bf16 hi/lo split =================================
__global__ __launch_bounds__(256) void split_kernel(
    const float4* __restrict__ in, __nv_bfloat162* __restrict__ oh,
    __nv_bfloat162* __restrict__ ol, int n4)
{
    int i = blockIdx.x * 256 + threadIdx.x;
    if (i >= n4) return;
    float4 v = in[i];
    __nv_bfloat16 h0 = __float2bfloat16(v.x), h1 = __float2bfloat16(v.y);
    __nv_bfloat16 h2 = __float2bfloat16(v.z), h3 = __float2bfloat16(v.w);
    __nv_bfloat162 a, b, c, d;
    a.x = h0; a.y = h1; b.x = h2; b.y = h3;
    c.x = __float2bfloat16(v.x - __bfloat162float(h0));
    c.y = __float2bfloat16(v.y - __bfloat162float(h1));
    d.x = __float2bfloat16(v.z - __bfloat162float(h2));
    d.y = __float2bfloat16(v.w - __bfloat162float(h3));
    oh[2 * i] = a; oh[2 * i + 1] = b;
    ol[2 * i] = c; ol[2 * i + 1] = d;
}

// W[K,N] fp32 -> hi/lo bf16 [N,K] (transpose + split)
__global__ __launch_bounds__(256) void split_tr_kernel(
    const float* __restrict__ W, __nv_bfloat16* __restrict__ oh,
    __nv_bfloat16* __restrict__ ol, int K, int N)
{
    __shared__ float t[32][33];
    const int bx = blockIdx.x, by = blockIdx.y;
    const int tx = threadIdx.x, ty = threadIdx.y;   // 32 x 8
    #pragma unroll
    for (int i = 0; i < 4; i++) {
        int rr = ty + i * 8;
        t[rr][tx] = W[(size_t)(by * 32 + rr) * N + bx * 32 + tx];
    }
    __syncthreads();
    #pragma unroll
    for (int i = 0; i < 4; i++) {
        int rr = ty + i * 8;
        float v = t[tx][rr];
        __nv_bfloat16 h = __float2bfloat16(v);
        size_t o = (size_t)(bx * 32 + rr) * K + by * 32 + tx;
        oh[o] = h;
        ol[o] = __float2bfloat16(v - __bfloat162float(h));
    }
}

// ================= Flash attention (fp32, unchanged) ========================
__global__ __launch_bounds__(256) void attn_kernel(
    const float* __restrict__ Q, const float* __restrict__ K,
    const float* __restrict__ V, const float* __restrict__ mask,
    float* __restrict__ O)
{
    extern __shared__ float sm[];
    float* Qs   = sm;
    float* Ks   = Qs + 64 * 64;
    float* Vs   = Ks + 64 * 65;
    float* Sx   = Vs + 64 * 65;
    float* mrow = Sx + 64 * 64;
    float* lrow = mrow + 64;
    float* frow = lrow + 64;

    const int tid  = threadIdx.x;
    const int tx   = tid & 15;
    const int ty   = tid >> 4;
    const int lane = tid & 31;
    const int warp = tid >> 5;

    const int qt = blockIdx.x;
    const int bh = blockIdx.y;
    const int b  = bh / HH;
    const int h  = bh % HH;

    const float* qbase = Q + ((size_t)b * SS + (size_t)qt * 64) * DD + h * DHH;
    const float* kbase = K + (size_t)b * SS * DD + h * DHH;
    const float* vbase = V + (size_t)b * SS * DD + h * DHH;
    const float* mbase = mask + (size_t)b * SS;

    for (int i = tid; i < 64 * 16; i += 256) {
        int rr = i >> 4, c4 = (i & 15) * 4;
        *(float4*)(Qs + rr * 64 + c4) =
            *(const float4*)(qbase + (size_t)rr * DD + c4);
    }
    if (tid < 64) { mrow[tid] = -INFINITY; lrow[tid] = 0.f; }

    float o[4][4];
    #pragma unroll
    for (int i = 0; i < 4; i++)
        #pragma unroll
        for (int j = 0; j < 4; j++) o[i][j] = 0.f;

    for (int t = 0; t < 16; t++) {
        __syncthreads();
        const float* kp = kbase + (size_t)(t * 64) * DD;
        const float* vp = vbase + (size_t)(t * 64) * DD;
        for (int i = tid; i < 64 * 16; i += 256) {
            int rr = i >> 4, c4 = (i & 15) * 4;
            float4 kv = *(const float4*)(kp + (size_t)rr * DD + c4);
            float* kd = Ks + rr * 65 + c4;
            kd[0] = kv.x; kd[1] = kv.y; kd[2] = kv.z; kd[3] = kv.w;
            float4 vv = *(const float4*)(vp + (size_t)rr * DD + c4);
            float* vd = Vs + rr * 65 + c4;
            vd[0] = vv.x; vd[1] = vv.y; vd[2] = vv.z; vd[3] = vv.w;
        }
        __syncthreads();

        float s[4][4];
        #pragma unroll
        for (int i = 0; i < 4; i++)
            #pragma unroll
            for (int j = 0; j < 4; j++) s[i][j] = 0.f;
        #pragma unroll 8
        for (int kk = 0; kk < 64; kk++) {
            float ra[4], rb[4];
            #pragma unroll
            for (int i = 0; i < 4; i++) ra[i] = Qs[(ty * 4 + i) * 64 + kk];
            #pragma unroll
            for (int j = 0; j < 4; j++) rb[j] = Ks[(tx * 4 + j) * 65 + kk];
            #pragma unroll
            for (int i = 0; i < 4; i++)
                #pragma unroll
                for (int j = 0; j < 4; j++)
                    s[i][j] += ra[i] * rb[j];
        }

        #pragma unroll
        for (int i = 0; i < 4; i++)
            #pragma unroll
            for (int j = 0; j < 4; j++) {
                int kcol = t * 64 + tx * 4 + j;
                Sx[(ty * 4 + i) * 64 + tx * 4 + j] =
                    s[i][j] * 0.125f + mbase[kcol] * (-1e9f);
            }
        __syncwarp();

        #pragma unroll
        for (int rr = 0; rr < 8; rr++) {
            int rI = warp * 8 + rr;
            float v0 = Sx[rI * 64 + lane];
            float v1 = Sx[rI * 64 + 32 + lane];
            float tm = fmaxf(v0, v1);
            #pragma unroll
            for (int off = 16; off; off >>= 1)
                tm = fmaxf(tm, __shfl_xor_sync(0xffffffffu, tm, off));
            float mprev = mrow[rI];
            float nm = fmaxf(mprev, tm);
            float e0 = __expf(v0 - nm);
            float e1 = __expf(v1 - nm);
            Sx[rI * 64 + lane]      = e0;
            Sx[rI * 64 + 32 + lane] = e1;
            float sum = e0 + e1;
            #pragma unroll
            for (int off = 16; off; off >>= 1)
                sum += __shfl_xor_sync(0xffffffffu, sum, off);
            if (lane == 0) {
                float f = __expf(mprev - nm);
                frow[rI] = f;
                lrow[rI] = lrow[rI] * f + sum;
                mrow[rI] = nm;
            }
        }
        __syncwarp();

        float f[4];
        #pragma unroll
        for (int i = 0; i < 4; i++) f[i] = frow[ty * 4 + i];
        #pragma unroll
        for (int i = 0; i < 4; i++)
            #pragma unroll
            for (int j = 0; j < 4; j++) o[i][j] *= f[i];

        #pragma unroll 8
        for (int kk = 0; kk < 64; kk++) {
            float ra[4], rb[4];
            #pragma unroll
            for (int i = 0; i < 4; i++) ra[i] = Sx[(ty * 4 + i) * 64 + kk];
            #pragma unroll
            for (int j = 0; j < 4; j++) rb[j] = Vs[kk * 65 + tx * 4 + j];
            #pragma unroll
            for (int i = 0; i < 4; i++)
                #pragma unroll
                for (int j = 0; j < 4; j++)
                    o[i][j] += ra[i] * rb[j];
        }
    }

    #pragma unroll
    for (int i = 0; i < 4; i++) {
        int row = ty * 4 + i;
        float linv = 1.f / lrow[row];
        float4 ov;
        ov.x = o[i][0] * linv;
        ov.y = o[i][1] * linv;
        ov.z = o[i][2] * linv;
        ov.w = o[i][3] * linv;
        size_t idx = ((size_t)b * SS + (size_t)qt * 64 + row) * DD
                   + h * DHH + tx * 4;
        *(float4*)(O + idx) = ov;
    }
}

// ================= residual + LayerNorm (optional fused bf16 split) ========
template<int SPL>
__global__ __launch_bounds__(256) void residual_ln_kernel(
    const float* __restrict__ X, const float* __restrict__ Y,
    const float* __restrict__ g, const float* __restrict__ beta,
    float* __restrict__ out,
    __nv_bfloat16* __restrict__ oh, __nv_bfloat16* __restrict__ ol)
{
    __shared__ float ws[8], ws2[8];
    const int row = blockIdx.x;
    const int tid = threadIdx.x;
    const int lane = tid & 31, warp = tid >> 5;
    const float* px = X + (size_t)row * DD;
    const float* py = Y + (size_t)row * DD;

    float v[4];
    float s = 0.f, s2 = 0.f;
    #pragma unroll
    for (int l = 0; l < 4; l++) {
        int c = tid + l * 256;
        float t = px[c] + py[c];
        v[l] = t; s += t; s2 += t * t;
    }
    #pragma unroll
    for (int off = 16; off; off >>= 1) {
        s  += __shfl_xor_sync(0xffffffffu, s,  off);
        s2 += __shfl_xor_sync(0xffffffffu, s2, off);
    }
    if (lane == 0) { ws[warp] = s; ws2[warp] = s2; }
    __syncthreads();
    if (warp == 0) {
        s  = (lane < 8) ? ws[lane]  : 0.f;
        s2 = (lane < 8) ? ws2[lane] : 0.f;
        #pragma unroll
        for (int off = 4; off; off >>= 1) {
            s  += __shfl_xor_sync(0xffffffffu, s,  off);
            s2 += __shfl_xor_sync(0xffffffffu, s2, off);
        }
        if (lane == 0) { ws[0] = s; ws2[0] = s2; }
    }
    __syncthreads();
    float mu  = ws[0] * (1.f / 1024.f);
    float var = fmaxf(ws2[0] * (1.f / 1024.f) - mu * mu, 0.f);
    float rstd = rsqrtf(var + 1e-6f);
    #pragma unroll
    for (int l = 0; l < 4; l++) {
        int c = tid + l * 256;
        float rv = g[c] * (v[l] - mu) * rstd + beta[c];
        out[(size_t)row * DD + c] = rv;
        if (SPL) {
            __nv_bfloat16 h = __float2bfloat16(rv);
            oh[(size_t)row * DD + c] = h;
            ol[(size_t)row * DD + c] =
                __float2bfloat16(rv - __bfloat162float(h));
        }
    }
}

// ================= launch ===================================================
extern "C" void kernel_launch(void* const* d_in, const int* in_sizes, int n_in,
                              void* d_out, int out_size)
{
    const float* x    = (const float*)d_in[0];
    const float* mask = (const float*)d_in[1];
    const float* Wq   = (const float*)d_in[2];
    const float* bq   = (const float*)d_in[3];
    const float* Wk   = (const float*)d_in[4];
    const float* bk   = (const float*)d_in[5];
    const float* Wv   = (const float*)d_in[6];
    const float* bv   = (const float*)d_in[7];
    const float* Wo   = (const float*)d_in[8];
    const float* bo   = (const float*)d_in[9];
    const float* g1   = (const float*)d_in[10];
    const float* be1  = (const float*)d_in[11];
    const float* W1   = (const float*)d_in[12];
    const float* bf1  = (const float*)d_in[13];
    const float* W2   = (const float*)d_in[14];
    const float* bf2  = (const float*)d_in[15];
    const float* g2   = (const float*)d_in[16];
    const float* be2  = (const float*)d_in[17];
    float* out = (float*)d_out;

    float *q, *k, *v, *ctx, *t1, *x1;
    __nv_bfloat16 *ah, *al, *hh, *hl, *wh, *wl;
    cudaGetSymbolAddress((void**)&q,   g_q);
    cudaGetSymbolAddress((void**)&k,   g_k);
    cudaGetSymbolAddress((void**)&v,   g_v);
    cudaGetSymbolAddress((void**)&ctx, g_ctx);
    cudaGetSymbolAddress((void**)&t1,  g_t1);
    cudaGetSymbolAddress((void**)&x1,  g_x1);
    cudaGetSymbolAddress((void**)&ah,  g_ah);
    cudaGetSymbolAddress((void**)&al,  g_al);
    cudaGetSymbolAddress((void**)&hh,  g_hh);
    cudaGetSymbolAddress((void**)&hl,  g_hl);
    cudaGetSymbolAddress((void**)&wh,  g_wh);
    cudaGetSymbolAddress((void**)&wl,  g_wl);

    const int attn_smem = (64 * 64 + 64 * 65 + 64 * 65 + 64 * 64 + 192) * 4;
    cudaFuncSetAttribute(attn_kernel,
                         cudaFuncAttributeMaxDynamicSharedMemorySize, attn_smem);
    cudaFuncSetAttribute(gemm_mma<0, 0>,
                         cudaFuncAttributeMaxDynamicSharedMemorySize, G_SMEM);
    cudaFuncSetAttribute(gemm_mma<1, 1>,
                         cudaFuncAttributeMaxDynamicSharedMemorySize, G_SMEM);

    const dim3 trDD(DD / 32, DD / 32);
    const dim3 trDF(FF / 32, DD / 32);   // W1: K=DD, N=FF
    const dim3 trFD(DD / 32, FF / 32);   // W2: K=FF, N=DD
    const dim3 tb(32, 8);
    const dim3 gD(DD / 128, MR / 128);   // (8, 64)
    const dim3 gF(FF / 128, MR / 128);   // (32, 64)

    // split x
    split_kernel<<<(MR * DD / 4 + 255) / 256, 256>>>(
        (const float4*)x, (__nv_bfloat162*)ah, (__nv_bfloat162*)al, MR * DD / 4);

    // QKV projections (tensor core)
    split_tr_kernel<<<trDD, tb>>>(Wq, wh, wl, DD, DD);
    gemm_mma<0, 0><<<gD, 256, G_SMEM>>>(ah, al, wh, wl, bq, q, nullptr, nullptr, DD, DD);
    split_tr_kernel<<<trDD, tb>>>(Wk, wh, wl, DD, DD);
    gemm_mma<0, 0><<<gD, 256, G_SMEM>>>(ah, al, wh, wl, bk, k, nullptr, nullptr, DD, DD);
    split_tr_kernel<<<trDD, tb>>>(Wv, wh, wl, DD, DD);
    gemm_mma<0, 0><<<gD, 256, G_SMEM>>>(ah, al, wh, wl, bv, v, nullptr, nullptr, DD, DD);

    // fused attention -> ctx [B,S,D]
    attn_kernel<<<dim3(16, 128), 256, attn_smem>>>(q, k, v, mask, ctx);

    // output projection + residual LN (LN emits split x1 for FFN1)
    split_kernel<<<(MR * DD / 4 + 255) / 256, 256>>>(
        (const float4*)ctx, (__nv_bfloat162*)ah, (__nv_bfloat162*)al, MR * DD / 4);
    split_tr_kernel<<<trDD, tb>>>(Wo, wh, wl, DD, DD);
    gemm_mma<0, 0><<<gD, 256, G_SMEM>>>(ah, al, wh, wl, bo, t1, nullptr, nullptr, DD, DD);
    residual_ln_kernel<1><<<MR, 256>>>(x, t1, g1, be1, x1, ah, al);

    // FFN1: relu(x1 @ W1 + bf1), epilogue writes split bf16 hidden directly
    split_tr_kernel<<<trDF, tb>>>(W1, wh, wl, DD, FF);
    gemm_mma<1, 1><<<gF, 256, G_SMEM>>>(ah, al, wh, wl, bf1, nullptr, hh, hl, FF, DD);

    // FFN2 + residual LN
    split_tr_kernel<<<trFD, tb>>>(W2, wh, wl, FF, DD);
    gemm_mma<0, 0><<<gD, 256, G_SMEM>>>(hh, hl, wh, wl, bf2, t1, nullptr, nullptr, DD, FF);
    residual_ln_kernel<0><<<MR, 256>>>(x1, t1, g2, be2, out, nullptr, nullptr);
}

// round 4
// speedup vs baseline: 3.2787x; 1.4838x over previous
#include <cuda_runtime.h>
#include <cuda_bf16.h>
#include <math.h>
#include <stddef.h>
#include <stdint.h>

// Problem dims (fixed by the reference)
#define BB   8
#define SS   1024
#define DD   1024
#define HH   16
#define DHH  64
#define FF   4096
#define MR   (BB*SS)   // 8192 rows

// ---------------- scratch (device globals; no allocation allowed) ----------
__device__ float g_t1 [MR*DD];
__device__ float g_x1 [MR*DD];

// bf16 split buffers
__device__ __nv_bfloat16 g_ah[MR*DD];            // activation hi (x / ctx / x1)
__device__ __nv_bfloat16 g_al[MR*DD];            // activation lo
__device__ __nv_bfloat16 g_qh[MR*DD];
__device__ __nv_bfloat16 g_ql[MR*DD];
__device__ __nv_bfloat16 g_kh[MR*DD];
__device__ __nv_bfloat16 g_kl[MR*DD];
__device__ __nv_bfloat16 g_vh[MR*DD];
__device__ __nv_bfloat16 g_vl[MR*DD];
__device__ __nv_bfloat16 g_hh[(size_t)MR*FF];    // FFN hidden hi
__device__ __nv_bfloat16 g_hl[(size_t)MR*FF];    // FFN hidden lo
__device__ __nv_bfloat16 g_wh[(size_t)DD*FF];    // weight hi, [N,K]
__device__ __nv_bfloat16 g_wl[(size_t)DD*FF];    // weight lo, [N,K]

// ================= PTX helpers (compute_103-safe: sm_80 features only) =====
__device__ __forceinline__ uint32_t smem_u32(const void* p) {
    uint32_t a;
    asm("{ .reg .u64 t; cvta.to.shared.u64 t, %1; cvt.u32.u64 %0, t; }"
        : "=r"(a) : "l"(p));
    return a;
}
__device__ __forceinline__ uint32_t sw128(uint32_t o) {
    return o ^ ((o >> 3) & 0x70);
}
__device__ __forceinline__ void cp16(uint32_t s, const void* g) {
    asm volatile("cp.async.cg.shared.global [%0], [%1], 16;" :: "r"(s), "l"(g));
}
#define CP_COMMIT()  asm volatile("cp.async.commit_group;" ::: "memory")
#define CP_WAIT0()   asm volatile("cp.async.wait_group 0;" ::: "memory")
#define CP_WAIT1()   asm volatile("cp.async.wait_group 1;" ::: "memory")

__device__ __forceinline__ void ldsm4(uint32_t* r, uint32_t addr) {
    asm volatile("ldmatrix.sync.aligned.m8n8.x4.shared.b16 {%0,%1,%2,%3}, [%4];"
                 : "=r"(r[0]), "=r"(r[1]), "=r"(r[2]), "=r"(r[3]) : "r"(addr));
}
__device__ __forceinline__ void ldsm4t(uint32_t* r, uint32_t addr) {
    asm volatile("ldmatrix.sync.aligned.m8n8.x4.trans.shared.b16 {%0,%1,%2,%3}, [%4];"
                 : "=r"(r[0]), "=r"(r[1]), "=r"(r[2]), "=r"(r[3]) : "r"(addr));
}
__device__ __forceinline__ void mma16816(float* d, const uint32_t* a,
                                         const uint32_t* b) {
    asm volatile(
        "mma.sync.aligned.m16n8k16.row.col.f32.bf16.bf16.f32 "
        "{%0,%1,%2,%3}, {%4,%5,%6,%7}, {%8,%9}, {%0,%1,%2,%3};"
        : "+f"(d[0]), "+f"(d[1]), "+f"(d[2]), "+f"(d[3])
        : "r"(a[0]), "r"(a[1]), "r"(a[2]), "r"(a[3]),
          "r"(b[0]), "r"(b[1]));
}
// pack (v0,v1) into bf16x2 hi + bf16x2 lo-residual
__device__ __forceinline__ void pack_hl(float v0, float v1,
                                        uint32_t& hi, uint32_t& lo) {
    __nv_bfloat162 h = __floats2bfloat162_rn(v0, v1);
    float h0 = __bfloat162float(h.x), h1 = __bfloat162float(h.y);
    __nv_bfloat162 l = __floats2bfloat162_rn(v0 - h0, v1 - h1);
    hi = *(uint32_t*)&h;
    lo = *(uint32_t*)&l;
}

// ================= mma.sync GEMM (unchanged from R3) ========================
#define G_STAGE  65536            // Ah 16K | Al 16K | Bh 16K | Bl 16K
#define G_SMEM   (2*G_STAGE)

template<int ACT, int SPLITOUT>
__global__ __launch_bounds__(256)
void gemm_mma(const __nv_bfloat16* __restrict__ Ah,
              const __nv_bfloat16* __restrict__ Al,
              const __nv_bfloat16* __restrict__ Bh,
              const __nv_bfloat16* __restrict__ Bl,
              const float* __restrict__ bias,
              float* __restrict__ C,
              __nv_bfloat16* __restrict__ Ch,
              __nv_bfloat16* __restrict__ Cl,
              int N, int K)
{
    extern __shared__ __align__(128) char smem[];
    const uint32_t sb = smem_u32(smem);
    const int tid  = threadIdx.x;
    const int wid  = tid >> 5;
    const int lane = tid & 31;
    const int wm   = wid & 3;
    const int wn   = wid >> 2;
    const int bc = blockIdx.x, br = blockIdx.y;

    const __nv_bfloat16* Ah_t = Ah + (size_t)br * 128 * K;
    const __nv_bfloat16* Al_t = Al + (size_t)br * 128 * K;
    const __nv_bfloat16* Bh_t = Bh + (size_t)bc * 128 * K;
    const __nv_bfloat16* Bl_t = Bl + (size_t)bc * 128 * K;
    const int NT = K >> 6;

    auto load_stage = [&](int kt, int s) {
        const uint32_t base = sb + s * G_STAGE;
        const int koff = kt * 64;
        #pragma unroll
        for (int t = 0; t < 4; t++) {
            int idx = t * 256 + tid;
            int row = idx >> 3, ch = idx & 7;
            uint32_t so = sw128((uint32_t)(row * 128 + ch * 16));
            size_t go = (size_t)row * K + koff + ch * 8;
            cp16(base +         so, Ah_t + go);
            cp16(base + 16384 + so, Al_t + go);
            cp16(base + 32768 + so, Bh_t + go);
            cp16(base + 49152 + so, Bl_t + go);
        }
        CP_COMMIT();
    };

    float acc[2][8][4];
    #pragma unroll
    for (int mi = 0; mi < 2; mi++)
        #pragma unroll
        for (int nj = 0; nj < 8; nj++)
            #pragma unroll
            for (int e = 0; e < 4; e++) acc[mi][nj][e] = 0.f;

    const int g = lane >> 3, r = lane & 7;

    load_stage(0, 0);

    for (int kt = 0; kt < NT; kt++) {
        const int buf = kt & 1;
        if (kt + 1 < NT) { load_stage(kt + 1, buf ^ 1); CP_WAIT1(); }
        else             { CP_WAIT0(); }
        __syncthreads();

        const uint32_t sA  = sb + buf * G_STAGE;
        const uint32_t sAl = sA + 16384;
        const uint32_t sBh = sA + 32768;
        const uint32_t sBl = sA + 49152;

        #pragma unroll
        for (int kc = 0; kc < 4; kc++) {
            uint32_t a_h[2][4], a_l[2][4];
            #pragma unroll
            for (int mi = 0; mi < 2; mi++) {
                int arow = wm * 32 + mi * 16 + r + ((g & 1) << 3);
                uint32_t off = sw128((uint32_t)(arow * 128 + kc * 32 +
                                                ((g >> 1) << 4)));
                ldsm4(a_h[mi], sA  + off);
                ldsm4(a_l[mi], sAl + off);
            }
            #pragma unroll
            for (int np = 0; np < 4; np++) {
                int brow = wn * 64 + np * 16 + r + ((g >> 1) << 3);
                uint32_t off = sw128((uint32_t)(brow * 128 + kc * 32 +
                                                ((g & 1) << 4)));
                uint32_t b_h[4], b_l[4];
                ldsm4(b_h, sBh + off);
                ldsm4(b_l, sBl + off);
                #pragma unroll
                for (int t = 0; t < 2; t++) {
                    int nj = np * 2 + t;
                    #pragma unroll
                    for (int mi = 0; mi < 2; mi++) {
                        mma16816(acc[mi][nj], a_h[mi], &b_h[2 * t]);
                        mma16816(acc[mi][nj], a_l[mi], &b_h[2 * t]);
                        mma16816(acc[mi][nj], a_h[mi], &b_l[2 * t]);
                    }
                }
            }
        }
        __syncthreads();
    }

    const int cbase = bc * 128 + wn * 64 + (lane & 3) * 2;
    const int rbase = br * 128 + wm * 32 + (lane >> 2);
    #pragma unroll
    for (int mi = 0; mi < 2; mi++) {
        #pragma unroll
        for (int nj = 0; nj < 8; nj++) {
            int c = cbase + nj * 8;
            float2 bv = *(const float2*)(bias + c);
            float v0 = acc[mi][nj][0] + bv.x;
            float v1 = acc[mi][nj][1] + bv.y;
            float v2 = acc[mi][nj][2] + bv.x;
            float v3 = acc[mi][nj][3] + bv.y;
            if (ACT) {
                v0 = fmaxf(v0, 0.f); v1 = fmaxf(v1, 0.f);
                v2 = fmaxf(v2, 0.f); v3 = fmaxf(v3, 0.f);
            }
            size_t i0 = (size_t)(rbase + mi * 16)     * N + c;
            size_t i1 = (size_t)(rbase + mi * 16 + 8) * N + c;
            if (SPLITOUT) {
                uint32_t h0, l0, h1, l1;
                pack_hl(v0, v1, h0, l0);
                pack_hl(v2, v3, h1, l1);
                *(uint32_t*)(Ch + i0) = h0;
                *(uint32_t*)(Ch + i1) = h1;
                *(uint32_t*)(Cl + i0) = l0;
                *(uint32_t*)(Cl + i1) = l1;
            } else {
                float2 o0; o0.x = v0; o0.y = v1;
                float2 o1; o1.x = v2; o1.y = v3;
                *(float2*)(C + i0) = o0;
                *(float2*)(C + i1) = o1;
            }
        }
    }
}

// ================= Flash attention on tensor cores ==========================
// Block = (b, h, 128-query tile). 8 warps, warp w owns query rows [16w,16w+16).
// S = QK^T via 3-term bf16 split mma; softmax warp-local in registers;
// PV via P hi/lo in-register A-fragments + ldmatrix.trans V fragments.
// K/V double-buffered cp.async. Writes split bf16 ctx (hi/lo) directly.
#define A_QH   0
#define A_QL   16384
#define A_ST   32768            // 2 stages x (Kh 8K | Kl 8K | Vh 8K | Vl 8K)
#define A_MK   98304            // 2 x 256 B mask
#define A_SMEM (98304 + 512)

__global__ __launch_bounds__(256)
void attn_mma(const __nv_bfloat16* __restrict__ qh,
              const __nv_bfloat16* __restrict__ ql,
              const __nv_bfloat16* __restrict__ kh,
              const __nv_bfloat16* __restrict__ kl,
              const __nv_bfloat16* __restrict__ vh,
              const __nv_bfloat16* __restrict__ vl,
              const float* __restrict__ mask,
              __nv_bfloat16* __restrict__ ch,
              __nv_bfloat16* __restrict__ cl)
{
    extern __shared__ __align__(128) char smem[];
    const uint32_t sb = smem_u32(smem);
    const int tid  = threadIdx.x;
    const int wid  = tid >> 5;
    const int lane = tid & 31;
    const int g    = lane >> 3, r8 = lane & 7;
    const int c2   = (lane & 3) * 2;

    const int qt = blockIdx.x;              // 0..7
    const int bh = blockIdx.y;              // 0..127
    const int b  = bh >> 4;
    const int h  = bh & 15;

    const size_t qrow0 = (size_t)b * SS + (size_t)qt * 128;
    const __nv_bfloat16* qhg = qh + qrow0 * DD + h * DHH;
    const __nv_bfloat16* qlg = ql + qrow0 * DD + h * DHH;
    const __nv_bfloat16* khg = kh + (size_t)b * SS * DD + h * DHH;
    const __nv_bfloat16* klg = kl + (size_t)b * SS * DD + h * DHH;
    const __nv_bfloat16* vhg = vh + (size_t)b * SS * DD + h * DHH;
    const __nv_bfloat16* vlg = vl + (size_t)b * SS * DD + h * DHH;
    const float* mkg = mask + (size_t)b * SS;

    auto load_kv = [&](int t, int s) {
        const uint32_t base = sb + A_ST + s * 32768;
        const size_t koff = (size_t)(t * 64) * DD;
        #pragma unroll
        for (int it = 0; it < 8; it++) {
            int idx = it * 256 + tid;            // 0..2047
            int mat = idx >> 9;                  // 0..3: Kh,Kl,Vh,Vl
            int sub = idx & 511;
            int row = sub >> 3, chk = sub & 7;
            uint32_t so = sw128((uint32_t)(row * 128 + chk * 16));
            size_t go = koff + (size_t)row * DD + chk * 8;
            const __nv_bfloat16* src =
                (mat == 0) ? khg : (mat == 1) ? klg : (mat == 2) ? vhg : vlg;
            cp16(base + mat * 8192 + so, src + go);
        }
        if (tid < 16)
            cp16(sb + A_MK + s * 256 + tid * 16, mkg + t * 64 + tid * 4);
        CP_COMMIT();
    };

    // Q tile load (group 0, together with stage 0)
    #pragma unroll
    for (int it = 0; it < 8; it++) {
        int idx = it * 256 + tid;                // 0..2047
        int mat = idx >> 10;                     // 0: qh, 1: ql
        int sub = idx & 1023;
        int row = sub >> 3, chk = sub & 7;
        uint32_t so = sw128((uint32_t)(row * 128 + chk * 16));
        size_t go = (size_t)row * DD + chk * 8;
        cp16(sb + (mat ? A_QL : A_QH) + so, (mat ? qlg : qhg) + go);
    }
    load_kv(0, 0);

    float mA = -INFINITY, mB = -INFINITY, lA = 0.f, lB = 0.f;
    float O[8][4];
    #pragma unroll
    for (int j = 0; j < 8; j++)
        #pragma unroll
        for (int e = 0; e < 4; e++) O[j][e] = 0.f;

    #pragma unroll 1
    for (int t = 0; t < 16; t++) {
        const int buf = t & 1;
        if (t + 1 < 16) { load_kv(t + 1, buf ^ 1); CP_WAIT1(); }
        else            { CP_WAIT0(); }
        __syncthreads();

        const uint32_t sKh = sb + A_ST + buf * 32768;
        const uint32_t sKl = sKh + 8192;
        const uint32_t sVh = sKh + 16384;
        const uint32_t sVl = sKh + 24576;
        const float* mkv = (const float*)(smem + A_MK + buf * 256);

        // ---- S = Q @ K^T (3-term) ----
        float s_[8][4];
        #pragma unroll
        for (int j = 0; j < 8; j++)
            #pragma unroll
            for (int e = 0; e < 4; e++) s_[j][e] = 0.f;

        #pragma unroll
        for (int kc = 0; kc < 4; kc++) {
            uint32_t aqh[4], aql[4];
            {
                int arow = wid * 16 + r8 + ((g & 1) << 3);
                uint32_t off = sw128((uint32_t)(arow * 128 + kc * 32 +
                                                ((g >> 1) << 4)));
                ldsm4(aqh, sb + A_QH + off);
                ldsm4(aql, sb + A_QL + off);
            }
            #pragma unroll
            for (int np = 0; np < 4; np++) {
                int brow = np * 16 + r8 + ((g >> 1) << 3);
                uint32_t off = sw128((uint32_t)(brow * 128 + kc * 32 +
                                                ((g & 1) << 4)));
                uint32_t bkh[4], bkl[4];
                ldsm4(bkh, sKh + off);
                ldsm4(bkl, sKl + off);
                #pragma unroll
                for (int t2 = 0; t2 < 2; t2++) {
                    int j = np * 2 + t2;
                    mma16816(s_[j], aqh, &bkh[2 * t2]);
                    mma16816(s_[j], aql, &bkh[2 * t2]);
                    mma16816(s_[j], aqh, &bkl[2 * t2]);
                }
            }
        }

        // ---- scale + mask, row max ----
        float tmA = -INFINITY, tmB = -INFINITY;
        #pragma unroll
        for (int j = 0; j < 8; j++) {
            float mk0 = mkv[j * 8 + c2]     * (-1e9f);
            float mk1 = mkv[j * 8 + c2 + 1] * (-1e9f);
            s_[j][0] = s_[j][0] * 0.125f + mk0;
            s_[j][1] = s_[j][1] * 0.125f + mk1;
            s_[j][2] = s_[j][2] * 0.125f + mk0;
            s_[j][3] = s_[j][3] * 0.125f + mk1;
            tmA = fmaxf(tmA, fmaxf(s_[j][0], s_[j][1]));
            tmB = fmaxf(tmB, fmaxf(s_[j][2], s_[j][3]));
        }
        tmA = fmaxf(tmA, __shfl_xor_sync(0xffffffffu, tmA, 1));
        tmA = fmaxf(tmA, __shfl_xor_sync(0xffffffffu, tmA, 2));
        tmB = fmaxf(tmB, __shfl_xor_sync(0xffffffffu, tmB, 1));
        tmB = fmaxf(tmB, __shfl_xor_sync(0xffffffffu, tmB, 2));

        const float nmA = fmaxf(mA, tmA), nmB = fmaxf(mB, tmB);
        const float fA = __expf(mA - nmA), fB = __expf(mB - nmB);

        // ---- p = exp(s - m), row sum ----
        float sumA = 0.f, sumB = 0.f;
        #pragma unroll
        for (int j = 0; j < 8; j++) {
            s_[j][0] = __expf(s_[j][0] - nmA);
            s_[j][1] = __expf(s_[j][1] - nmA);
            s_[j][2] = __expf(s_[j][2] - nmB);
            s_[j][3] = __expf(s_[j][3] - nmB);
            sumA += s_[j][0] + s_[j][1];
            sumB += s_[j][2] + s_[j][3];
        }
        sumA += __shfl_xor_sync(0xffffffffu, sumA, 1);
        sumA += __shfl_xor_sync(0xffffffffu, sumA, 2);
        sumB += __shfl_xor_sync(0xffffffffu, sumB, 1);
        sumB += __shfl_xor_sync(0xffffffffu, sumB, 2);
        lA = lA * fA + sumA;  mA = nmA;
        lB = lB * fB + sumB;  mB = nmB;

        // ---- rescale O ----
        #pragma unroll
        for (int j = 0; j < 8; j++) {
            O[j][0] *= fA; O[j][1] *= fA;
            O[j][2] *= fB; O[j][3] *= fB;
        }

        // ---- O += P @ V (3-term, P split in-register) ----
        #pragma unroll
        for (int c = 0; c < 4; c++) {
            uint32_t ap_h[4], ap_l[4];
            pack_hl(s_[2 * c][0],     s_[2 * c][1],     ap_h[0], ap_l[0]);
            pack_hl(s_[2 * c][2],     s_[2 * c][3],     ap_h[1], ap_l[1]);
            pack_hl(s_[2 * c + 1][0], s_[2 * c + 1][1], ap_h[2], ap_l[2]);
            pack_hl(s_[2 * c + 1][2], s_[2 * c + 1][3], ap_h[3], ap_l[3]);
            #pragma unroll
            for (int np2 = 0; np2 < 4; np2++) {
                int vrow = c * 16 + r8 + ((g & 1) << 3);
                uint32_t off = sw128((uint32_t)(vrow * 128 + np2 * 32 +
                                                ((g >> 1) << 4)));
                uint32_t bv_h[4], bv_l[4];
                ldsm4t(bv_h, sVh + off);
                ldsm4t(bv_l, sVl + off);
                #pragma unroll
                for (int t2 = 0; t2 < 2; t2++) {
                    int nj = np2 * 2 + t2;
                    mma16816(O[nj], ap_h, &bv_h[2 * t2]);
                    mma16816(O[nj], ap_l, &bv_h[2 * t2]);
                    mma16816(O[nj], ap_h, &bv_l[2 * t2]);
                }
            }
        }
        __syncthreads();
    }

    // ---- normalize, split, write ctx ----
    const float liA = 1.f / lA, liB = 1.f / lB;
    const size_t rowA = qrow0 + wid * 16 + (lane >> 2);
    const size_t rowB = rowA + 8;
    const int    colb = h * DHH + c2;
    #pragma unroll
    for (int j = 0; j < 8; j++) {
        uint32_t hi, lo;
        pack_hl(O[j][0] * liA, O[j][1] * liA, hi, lo);
        *(uint32_t*)(ch + rowA * DD + colb + j * 8) = hi;
        *(uint32_t*)(cl + rowA * DD + colb + j * 8) = lo;
        pack_hl(O[j][2] * liB, O[j][3] * liB, hi, lo);
        *(uint32_t*)(ch + rowB * DD + colb + j * 8) = hi;
        *(uint32_t*)(cl + rowB * DD + colb + j * 8) = lo;
    }
}

// ================= fp32 -> bf16 hi/lo split =================================
__global__ __launch_bounds__(256) void split_kernel(
    const float4* __restrict__ in, __nv_bfloat162* __restrict__ oh,
    __nv_bfloat162* __restrict__ ol, int n4)
{
    int i = blockIdx.x * 256 + threadIdx.x;
    if (i >= n4) return;
    float4 v = in[i];
    uint32_t h0, l0, h1, l1;
    pack_hl(v.x, v.y, h0, l0);
    pack_hl(v.z, v.w, h1, l1);
    oh[2 * i]     = *(__nv_bfloat162*)&h0;
    oh[2 * i + 1] = *(__nv_bfloat162*)&h1;
    ol[2 * i]     = *(__nv_bfloat162*)&l0;
    ol[2 * i + 1] = *(__nv_bfloat162*)&l1;
}

// W[K,N] fp32 -> hi/lo bf16 [N,K] (transpose + split)
__global__ __launch_bounds__(256) void split_tr_kernel(
    const float* __restrict__ W, __nv_bfloat16* __restrict__ oh,
    __nv_bfloat16* __restrict__ ol, int K, int N)
{
    __shared__ float t[32][33];
    const int bx = blockIdx.x, by = blockIdx.y;
    const int tx = threadIdx.x, ty = threadIdx.y;   // 32 x 8
    #pragma unroll
    for (int i = 0; i < 4; i++) {
        int rr = ty + i * 8;
        t[rr][tx] = W[(size_t)(by * 32 + rr) * N + bx * 32 + tx];
    }
    __syncthreads();
    #pragma unroll
    for (int i = 0; i < 4; i++) {
        int rr = ty + i * 8;
        float v = t[tx][rr];
        __nv_bfloat16 h = __float2bfloat16(v);
        size_t o = (size_t)(bx * 32 + rr) * K + by * 32 + tx;
        oh[o] = h;
        ol[o] = __float2bfloat16(v - __bfloat162float(h));
    }
}

// ================= residual + LayerNorm (optional fused bf16 split) ========
template<int SPL>
__global__ __launch_bounds__(256) void residual_ln_kernel(
    const float* __restrict__ X, const float* __restrict__ Y,
    const float* __restrict__ g, const float* __restrict__ beta,
    float* __restrict__ out,
    __nv_bfloat16* __restrict__ oh, __nv_bfloat16* __restrict__ ol)
{
    __shared__ float ws[8], ws2[8];
    const int row = blockIdx.x;
    const int tid = threadIdx.x;
    const int lane = tid & 31, warp = tid >> 5;
    const float* px = X + (size_t)row * DD;
    const float* py = Y + (size_t)row * DD;

    float v[4];
    float s = 0.f, s2 = 0.f;
    #pragma unroll
    for (int l = 0; l < 4; l++) {
        int c = tid + l * 256;
        float t = px[c] + py[c];
        v[l] = t; s += t; s2 += t * t;
    }
    #pragma unroll
    for (int off = 16; off; off >>= 1) {
        s  += __shfl_xor_sync(0xffffffffu, s,  off);
        s2 += __shfl_xor_sync(0xffffffffu, s2, off);
    }
    if (lane == 0) { ws[warp] = s; ws2[warp] = s2; }
    __syncthreads();
    if (warp == 0) {
        s  = (lane < 8) ? ws[lane]  : 0.f;
        s2 = (lane < 8) ? ws2[lane] : 0.f;
        #pragma unroll
        for (int off = 4; off; off >>= 1) {
            s  += __shfl_xor_sync(0xffffffffu, s,  off);
            s2 += __shfl_xor_sync(0xffffffffu, s2, off);
        }
        if (lane == 0) { ws[0] = s; ws2[0] = s2; }
    }
    __syncthreads();
    float mu  = ws[0] * (1.f / 1024.f);
    float var = fmaxf(ws2[0] * (1.f / 1024.f) - mu * mu, 0.f);
    float rstd = rsqrtf(var + 1e-6f);
    #pragma unroll
    for (int l = 0; l < 4; l++) {
        int c = tid + l * 256;
        float rv = g[c] * (v[l] - mu) * rstd + beta[c];
        out[(size_t)row * DD + c] = rv;
        if (SPL) {
            __nv_bfloat16 h = __float2bfloat16(rv);
            oh[(size_t)row * DD + c] = h;
            ol[(size_t)row * DD + c] =
                __float2bfloat16(rv - __bfloat162float(h));
        }
    }
}

// ================= launch ===================================================
extern "C" void kernel_launch(void* const* d_in, const int* in_sizes, int n_in,
                              void* d_out, int out_size)
{
    const float* x    = (const float*)d_in[0];
    const float* mask = (const float*)d_in[1];
    const float* Wq   = (const float*)d_in[2];
    const float* bq   = (const float*)d_in[3];
    const float* Wk   = (const float*)d_in[4];
    const float* bk   = (const float*)d_in[5];
    const float* Wv   = (const float*)d_in[6];
    const float* bv   = (const float*)d_in[7];
    const float* Wo   = (const float*)d_in[8];
    const float* bo   = (const float*)d_in[9];
    const float* g1   = (const float*)d_in[10];
    const float* be1  = (const float*)d_in[11];
    const float* W1   = (const float*)d_in[12];
    const float* bf1  = (const float*)d_in[13];
    const float* W2   = (const float*)d_in[14];
    const float* bf2  = (const float*)d_in[15];
    const float* g2   = (const float*)d_in[16];
    const float* be2  = (const float*)d_in[17];
    float* out = (float*)d_out;

    float *t1, *x1;
    __nv_bfloat16 *ah, *al, *qh, *ql, *kh, *kl, *vh, *vl, *hh, *hl, *wh, *wl;
    cudaGetSymbolAddress((void**)&t1,  g_t1);
    cudaGetSymbolAddress((void**)&x1,  g_x1);
    cudaGetSymbolAddress((void**)&ah,  g_ah);
    cudaGetSymbolAddress((void**)&al,  g_al);
    cudaGetSymbolAddress((void**)&qh,  g_qh);
    cudaGetSymbolAddress((void**)&ql,  g_ql);
    cudaGetSymbolAddress((void**)&kh,  g_kh);
    cudaGetSymbolAddress((void**)&kl,  g_kl);
    cudaGetSymbolAddress((void**)&vh,  g_vh);
    cudaGetSymbolAddress((void**)&vl,  g_vl);
    cudaGetSymbolAddress((void**)&hh,  g_hh);
    cudaGetSymbolAddress((void**)&hl,  g_hl);
    cudaGetSymbolAddress((void**)&wh,  g_wh);
    cudaGetSymbolAddress((void**)&wl,  g_wl);

    cudaFuncSetAttribute(attn_mma,
                         cudaFuncAttributeMaxDynamicSharedMemorySize, A_SMEM);
    cudaFuncSetAttribute(gemm_mma<0, 0>,
                         cudaFuncAttributeMaxDynamicSharedMemorySize, G_SMEM);
    cudaFuncSetAttribute(gemm_mma<0, 1>,
                         cudaFuncAttributeMaxDynamicSharedMemorySize, G_SMEM);
    cudaFuncSetAttribute(gemm_mma<1, 1>,
                         cudaFuncAttributeMaxDynamicSharedMemorySize, G_SMEM);

    const dim3 trDD(DD / 32, DD / 32);
    const dim3 trDF(FF / 32, DD / 32);   // W1: K=DD, N=FF
    const dim3 trFD(DD / 32, FF / 32);   // W2: K=FF, N=DD
    const dim3 tb(32, 8);
    const dim3 gD(DD / 128, MR / 128);   // (8, 64)
    const dim3 gF(FF / 128, MR / 128);   // (32, 64)

    // split x -> ah/al
    split_kernel<<<(MR * DD / 4 + 255) / 256, 256>>>(
        (const float4*)x, (__nv_bfloat162*)ah, (__nv_bfloat162*)al, MR * DD / 4);

    // QKV projections: epilogue emits split bf16 q/k/v directly
    split_tr_kernel<<<trDD, tb>>>(Wq, wh, wl, DD, DD);
    gemm_mma<0, 1><<<gD, 256, G_SMEM>>>(ah, al, wh, wl, bq, nullptr, qh, ql, DD, DD);
    split_tr_kernel<<<trDD, tb>>>(Wk, wh, wl, DD, DD);
    gemm_mma<0, 1><<<gD, 256, G_SMEM>>>(ah, al, wh, wl, bk, nullptr, kh, kl, DD, DD);
    split_tr_kernel<<<trDD, tb>>>(Wv, wh, wl, DD, DD);
    gemm_mma<0, 1><<<gD, 256, G_SMEM>>>(ah, al, wh, wl, bv, nullptr, vh, vl, DD, DD);

    // fused tensor-core attention -> split ctx into ah/al (x split no longer needed)
    attn_mma<<<dim3(8, 128), 256, A_SMEM>>>(qh, ql, kh, kl, vh, vl, mask, ah, al);

    // output projection + residual LN (LN emits split x1 for FFN1)
    split_tr_kernel<<<trDD, tb>>>(Wo, wh, wl, DD, DD);
    gemm_mma<0, 0><<<gD, 256, G_SMEM>>>(ah, al, wh, wl, bo, t1, nullptr, nullptr, DD, DD);
    residual_ln_kernel<1><<<MR, 256>>>(x, t1, g1, be1, x1, ah, al);

    // FFN1: relu(x1 @ W1 + bf1), epilogue writes split bf16 hidden directly
    split_tr_kernel<<<trDF, tb>>>(W1, wh, wl, DD, FF);
    gemm_mma<1, 1><<<gF, 256, G_SMEM>>>(ah, al, wh, wl, bf1, nullptr, hh, hl, FF, DD);

    // FFN2 + residual LN
    split_tr_kernel<<<trFD, tb>>>(W2, wh, wl, FF, DD);
    gemm_mma<0, 0><<<gD, 256, G_SMEM>>>(hh, hl, wh, wl, bf2, t1, nullptr, nullptr, DD, FF);
    residual_ln_kernel<0><<<MR, 256>>>(x1, t1, g2, be2, out, nullptr, nullptr);
}